// round 7
// baseline (speedup 1.0000x reference)
#include <cuda_runtime.h>
#include <cstdint>
#include <cstddef>

#define Lc 1024
#define Bc 8192
#define SPLITW 21            // prefix windows (21*32 = 672 steps)

// epsT[i*256 + d*128 + m]
__device__ __align__(16) float    g_epsT[Lc * 256];
// xpack[w*Bc + b] = bitmask of inputs[b, 32w .. 32w+31]
__device__ __align__(16) uint32_t g_xpack[(Lc / 32) * Bc];

__global__ void prep_eps(const float* __restrict__ eps) {
    int idx = blockIdx.x * 256 + threadIdx.x;   // idx = i*256 + dm
    int dm = idx & 255;
    int i  = idx >> 8;
    g_epsT[idx] = eps[(dm << 10) + i];          // eps[(d*128+m)*1024 + i]
}

__global__ void prep_x(const int* __restrict__ x) {
    int b   = blockIdx.x;
    int wid = threadIdx.x >> 5;
    int k   = threadIdx.x & 31;
#pragma unroll
    for (int r = 0; r < 4; r++) {
        int w = wid + (r << 3);
        int v = x[(size_t)b * Lc + (w << 5) + k];
        unsigned mask = __ballot_sync(0xffffffffu, v != 0);
        if (k == 0) g_xpack[w * Bc + b] = mask;
    }
}

__global__ void zero_out(float* __restrict__ out) {
    out[blockIdx.x * 256 + threadIdx.x] = 0.0f;
}

static __device__ __forceinline__ uint64_t mul2(uint64_t a, uint64_t b) {
    uint64_t d; asm("mul.rn.f32x2 %0, %1, %2;" : "=l"(d) : "l"(a), "l"(b)); return d;
}
static __device__ __forceinline__ uint64_t fma2(uint64_t a, uint64_t b, uint64_t c) {
    uint64_t d; asm("fma.rn.f32x2 %0, %1, %2, %3;" : "=l"(d) : "l"(a), "l"(b), "l"(c)); return d;
}
static __device__ __forceinline__ float hadd2(uint64_t v) {
    float x, y; asm("mov.b64 {%0,%1}, %2;" : "=f"(x), "=f"(y) : "l"(v)); return x + y;
}
static __device__ __forceinline__ float ex2f(float x) {
    float y; asm("ex2.approx.ftz.f32 %0, %1;" : "=f"(y) : "f"(x)); return y;
}
static __device__ __forceinline__ float lg2f(float x) {
    float y; asm("lg2.approx.ftz.f32 %0, %1;" : "=f"(y) : "f"(x)); return y;
}

__global__ __launch_bounds__(32)
void arqgps_main(float* __restrict__ out) {
    const int l    = threadIdx.x;        // 32-thread block: 1 warp = 4 batches (half seq)
    const int grp  = blockIdx.x >> 1;
    const int half = blockIdx.x & 1;
    const int b0   = grp * 4;
    const int perm = l & 3;              // slot sp tracks batch sp^perm; term-batch = perm

    const uint64_t ONE2  = 0x3f8000003f800000ull;
    const uint64_t NEG12 = 0xbf800000bf800000ull;

    uint64_t gx[4], gy[4];
#pragma unroll
    for (int sp = 0; sp < 4; sp++) { gx[sp] = ONE2; gy[sp] = ONE2; }

    float acc  = 0.0f;
    int   cnt0 = 0;

    const ulonglong2* e0p = (const ulonglong2*)g_epsT + l;        // d=0, m 4l..4l+3
    const ulonglong2* e1p = e0p + 32;                             // d=1

    int wbeg = 0, wend = SPLITW;
    if (half) {
        // ---- g-only prefix: rebuild g(672) and cnt0(672), no reduction/term ----
        for (int w = 0; w < SPLITW; w++) {
            uint32_t xq0 = __ldg(g_xpack + w * Bc + b0 + (0 ^ perm));
            uint32_t xq1 = __ldg(g_xpack + w * Bc + b0 + (1 ^ perm));
            uint32_t xq2 = __ldg(g_xpack + w * Bc + b0 + (2 ^ perm));
            uint32_t xq3 = __ldg(g_xpack + w * Bc + b0 + (3 ^ perm));
            cnt0 += 32 - __popc(xq0);                 // zeros of term-batch
#pragma unroll 8
            for (int k = 0; k < 32; k++) {
                const int i = (w << 5) + k;
                ulonglong2 E0 = __ldg(e0p + (size_t)i * 64);
                ulonglong2 E1 = __ldg(e1p + (size_t)i * 64);
                const uint32_t bitm = 1u << k;
                const bool p0b = (xq0 & bitm) != 0;
                const bool p1b = (xq1 & bitm) != 0;
                const bool p2b = (xq2 & bitm) != 0;
                const bool p3b = (xq3 & bitm) != 0;
                gx[0] = mul2(gx[0], p0b ? E1.x : E0.x);
                gy[0] = mul2(gy[0], p0b ? E1.y : E0.y);
                gx[1] = mul2(gx[1], p1b ? E1.x : E0.x);
                gy[1] = mul2(gy[1], p1b ? E1.y : E0.y);
                gx[2] = mul2(gx[2], p2b ? E1.x : E0.x);
                gy[2] = mul2(gy[2], p2b ? E1.y : E0.y);
                gx[3] = mul2(gx[3], p3b ? E1.x : E0.x);
                gy[3] = mul2(gy[3], p3b ? E1.y : E0.y);
            }
        }
        wbeg = SPLITW; wend = Lc / 32;
    }

    for (int w = wbeg; w < wend; w++) {
        uint32_t xq0 = __ldg(g_xpack + w * Bc + b0 + (0 ^ perm));
        uint32_t xq1 = __ldg(g_xpack + w * Bc + b0 + (1 ^ perm));
        uint32_t xq2 = __ldg(g_xpack + w * Bc + b0 + (2 ^ perm));
        uint32_t xq3 = __ldg(g_xpack + w * Bc + b0 + (3 ^ perm));

#pragma unroll 4
        for (int k = 0; k < 32; k++) {
            const int i = (w << 5) + k;
            ulonglong2 E0 = __ldg(e0p + (size_t)i * 64);
            ulonglong2 E1 = __ldg(e1p + (size_t)i * 64);

            // ED = E0 - E1 (shared): delta-dot needs only this
            const uint64_t EDx = fma2(E1.x, NEG12, E0.x);
            const uint64_t EDy = fma2(E1.y, NEG12, E0.y);

            const uint32_t bitm = 1u << k;
            const bool p0b = (xq0 & bitm) != 0;
            const bool p1b = (xq1 & bitm) != 0;
            const bool p2b = (xq2 & bitm) != 0;
            const bool p3b = (xq3 & bitm) != 0;

            float v[4];
            {
                uint64_t pd = fma2(EDy, gy[0], mul2(EDx, gx[0]));
                gx[0] = mul2(gx[0], p0b ? E1.x : E0.x);
                gy[0] = mul2(gy[0], p0b ? E1.y : E0.y);
                v[0] = hadd2(pd);
            }
            {
                uint64_t pd = fma2(EDy, gy[1], mul2(EDx, gx[1]));
                gx[1] = mul2(gx[1], p1b ? E1.x : E0.x);
                gy[1] = mul2(gy[1], p1b ? E1.y : E0.y);
                v[1] = hadd2(pd);
            }
            {
                uint64_t pd = fma2(EDy, gy[2], mul2(EDx, gx[2]));
                gx[2] = mul2(gx[2], p2b ? E1.x : E0.x);
                gy[2] = mul2(gy[2], p2b ? E1.y : E0.y);
                v[2] = hadd2(pd);
            }
            {
                uint64_t pd = fma2(EDy, gy[3], mul2(EDx, gx[3]));
                gx[3] = mul2(gx[3], p3b ? E1.x : E0.x);
                gy[3] = mul2(gy[3], p3b ? E1.y : E0.y);
                v[3] = hadd2(pd);
            }

            // XOR-permuted butterfly: slot s tracks batch s^(l&3)
            v[0] += __shfl_xor_sync(0xffffffffu, v[2], 2);
            v[1] += __shfl_xor_sync(0xffffffffu, v[3], 2);
            v[0] += __shfl_xor_sync(0xffffffffu, v[1], 1);
            v[0] += __shfl_xor_sync(0xffffffffu, v[0], 4);
            v[0] += __shfl_xor_sync(0xffffffffu, v[0], 8);
            v[0] += __shfl_xor_sync(0xffffffffu, v[0], 16);

            const float delta = v[0];             // s0 - s1 for batch (l&3)
            const bool  x1    = p0b;

            // term = min(0, x1?-delta:delta) - 0.5*ln(1+exp(-2|delta|))
            const float t    = x1 ? delta : -delta;
            const float relu = fmaxf(t, 0.0f);
            const float z    = ex2f(fabsf(delta) * -2.8853902f);
            float term = -relu - 0.34657359f * lg2f(1.0f + z);

            const int cOther = x1 ? cnt0 : (i - cnt0);
            if (cOther >= 512) term = 0.0f;
            acc += term;
            cnt0 += x1 ? 0 : 1;
        }
    }

    if (l < 4)
        atomicAdd(out + b0 + l, acc);
}

extern "C" void kernel_launch(void* const* d_in, const int* in_sizes, int n_in,
                              void* d_out, int out_size) {
    (void)n_in; (void)out_size;
    const int*   inputs;
    const float* eps;
    if (in_sizes[0] == Bc * Lc) {
        inputs = (const int*)d_in[0];
        eps    = (const float*)d_in[1];
    } else {
        inputs = (const int*)d_in[1];
        eps    = (const float*)d_in[0];
    }
    float* out = (float*)d_out;

    prep_eps<<<Lc, 256>>>(eps);
    prep_x<<<Bc, 256>>>(inputs);
    zero_out<<<Bc / 256, 256>>>(out);

    arqgps_main<<<(Bc / 4) * 2, 32>>>(out);
}

// round 8
// speedup vs baseline: 1.4647x; 1.4647x over previous
#include <cuda_runtime.h>
#include <cstdint>
#include <cstddef>

#define Lc 1024
#define Bc 8192

// epsT[i*256 + d*128 + m]
__device__ __align__(16) float    g_epsT[Lc * 256];
// xpack[w*Bc + b] = bitmask of inputs[b, 32w .. 32w+31]
__device__ __align__(16) uint32_t g_xpack[(Lc / 32) * Bc];

__global__ void prep_eps(const float* __restrict__ eps) {
    int idx = blockIdx.x * 256 + threadIdx.x;   // idx = i*256 + dm
    int dm = idx & 255;
    int i  = idx >> 8;
    g_epsT[idx] = eps[(dm << 10) + i];          // eps[(d*128+m)*1024 + i]
}

__global__ void prep_x(const int* __restrict__ x) {
    int b   = blockIdx.x;
    int wid = threadIdx.x >> 5;
    int k   = threadIdx.x & 31;
#pragma unroll
    for (int r = 0; r < 4; r++) {
        int w = wid + (r << 3);
        int v = x[(size_t)b * Lc + (w << 5) + k];
        unsigned mask = __ballot_sync(0xffffffffu, v != 0);
        if (k == 0) g_xpack[w * Bc + b] = mask;
    }
}

static __device__ __forceinline__ uint64_t mul2(uint64_t a, uint64_t b) {
    uint64_t d; asm("mul.rn.f32x2 %0, %1, %2;" : "=l"(d) : "l"(a), "l"(b)); return d;
}
static __device__ __forceinline__ uint64_t fma2(uint64_t a, uint64_t b, uint64_t c) {
    uint64_t d; asm("fma.rn.f32x2 %0, %1, %2, %3;" : "=l"(d) : "l"(a), "l"(b), "l"(c)); return d;
}
static __device__ __forceinline__ float hadd2(uint64_t v) {
    float x, y; asm("mov.b64 {%0,%1}, %2;" : "=f"(x), "=f"(y) : "l"(v)); return x + y;
}
static __device__ __forceinline__ float ex2f(float x) {
    float y; asm("ex2.approx.ftz.f32 %0, %1;" : "=f"(y) : "f"(x)); return y;
}
static __device__ __forceinline__ float lg2f(float x) {
    float y; asm("lg2.approx.ftz.f32 %0, %1;" : "=f"(y) : "f"(x)); return y;
}

__global__ __launch_bounds__(32)
void arqgps_main(float* __restrict__ out) {
    const int l    = threadIdx.x;        // 1 warp = 4 batches
    const int b0   = blockIdx.x * 4;
    const int perm = l & 3;              // slot sp tracks batch sp^perm; term-batch = perm
    const int js   = l >> 2;             // this lane's step-offset within each 8-step block
    const bool h4  = (l & 4)  != 0;
    const bool h8  = (l & 8)  != 0;
    const bool h16 = (l & 16) != 0;

    const uint64_t ONE2  = 0x3f8000003f800000ull;
    const uint64_t NEG12 = 0xbf800000bf800000ull;

    uint64_t gx[4], gy[4];
#pragma unroll
    for (int sp = 0; sp < 4; sp++) { gx[sp] = ONE2; gy[sp] = ONE2; }

    float acc       = 0.0f;
    int   cnt0_base = 0;                 // zeros of term-batch before current window

    const ulonglong2* e0p = (const ulonglong2*)g_epsT + l;        // d=0, m 4l..4l+3
    const ulonglong2* e1p = e0p + 32;                             // d=1

    for (int w = 0; w < Lc / 32; w++) {
        const uint32_t xq0 = __ldg(g_xpack + w * Bc + b0 + (0 ^ perm));
        const uint32_t xq1 = __ldg(g_xpack + w * Bc + b0 + (1 ^ perm));
        const uint32_t xq2 = __ldg(g_xpack + w * Bc + b0 + (2 ^ perm));
        const uint32_t xq3 = __ldg(g_xpack + w * Bc + b0 + (3 ^ perm));

        for (int K8 = 0; K8 < 32; K8 += 8) {
            const uint32_t x0w = xq0 >> K8;      // 8 relevant bits per mask
            const uint32_t x1w = xq1 >> K8;
            const uint32_t x2w = xq2 >> K8;
            const uint32_t x3w = xq3 >> K8;

            float u[8];
#pragma unroll
            for (int j = 0; j < 8; j++) {
                const int i = (w << 5) + K8 + j;
                ulonglong2 E0 = __ldg(e0p + (size_t)i * 64);
                ulonglong2 E1 = __ldg(e1p + (size_t)i * 64);

                const uint64_t EDx = fma2(E1.x, NEG12, E0.x);    // E0-E1
                const uint64_t EDy = fma2(E1.y, NEG12, E0.y);

                const uint32_t bj = 1u << j;
                const bool p0b = (x0w & bj) != 0;
                const bool p1b = (x1w & bj) != 0;
                const bool p2b = (x2w & bj) != 0;
                const bool p3b = (x3w & bj) != 0;

                uint64_t pd0 = fma2(EDy, gy[0], mul2(EDx, gx[0]));
                uint64_t pd1 = fma2(EDy, gy[1], mul2(EDx, gx[1]));
                uint64_t pd2 = fma2(EDy, gy[2], mul2(EDx, gx[2]));
                uint64_t pd3 = fma2(EDy, gy[3], mul2(EDx, gx[3]));

                gx[0] = mul2(gx[0], p0b ? E1.x : E0.x);
                gy[0] = mul2(gy[0], p0b ? E1.y : E0.y);
                gx[1] = mul2(gx[1], p1b ? E1.x : E0.x);
                gy[1] = mul2(gy[1], p1b ? E1.y : E0.y);
                gx[2] = mul2(gx[2], p2b ? E1.x : E0.x);
                gy[2] = mul2(gy[2], p2b ? E1.y : E0.y);
                gx[3] = mul2(gx[3], p3b ? E1.x : E0.x);
                gy[3] = mul2(gy[3], p3b ? E1.y : E0.y);

                float v0 = hadd2(pd0);
                float v1 = hadd2(pd1);
                float v2 = hadd2(pd2);
                float v3 = hadd2(pd3);

                // slot-combine: after these 3 shfls v0 = partial delta for
                // batch (l&3) over the 16 m's of this aligned 4-lane group
                v0 += __shfl_xor_sync(0xffffffffu, v2, 2);
                v1 += __shfl_xor_sync(0xffffffffu, v3, 2);
                v0 += __shfl_xor_sync(0xffffffffu, v1, 1);
                u[j] = v0;
            }

            // ---- fold 8 steps across lane groups ----
            // bit2 level: pairs (u0,u1)(u2,u3)(u4,u5)(u6,u7)
            float a0, a1, a2, a3, s;
            a0 = h4 ? u[1] : u[0]; s = h4 ? u[0] : u[1];
            a0 += __shfl_xor_sync(0xffffffffu, s, 4);
            a1 = h4 ? u[3] : u[2]; s = h4 ? u[2] : u[3];
            a1 += __shfl_xor_sync(0xffffffffu, s, 4);
            a2 = h4 ? u[5] : u[4]; s = h4 ? u[4] : u[5];
            a2 += __shfl_xor_sync(0xffffffffu, s, 4);
            a3 = h4 ? u[7] : u[6]; s = h4 ? u[6] : u[7];
            a3 += __shfl_xor_sync(0xffffffffu, s, 4);
            // bit3 level: pairs (a0,a1)(a2,a3)
            float c0, c1;
            c0 = h8 ? a1 : a0; s = h8 ? a0 : a1;
            c0 += __shfl_xor_sync(0xffffffffu, s, 8);
            c1 = h8 ? a3 : a2; s = h8 ? a2 : a3;
            c1 += __shfl_xor_sync(0xffffffffu, s, 8);
            // bit4 level: (c0,c1)
            float c = h16 ? c1 : c0; s = h16 ? c0 : c1;
            c += __shfl_xor_sync(0xffffffffu, s, 16);
            // c = full-128m delta for batch (l&3), step K8+js

            // ---- per-lane term for its (batch, step) ----
            const int  kk = K8 + js;                     // step within window
            const int  i  = (w << 5) + kk;
            const bool x1 = ((xq0 >> kk) & 1u) != 0;
            const int  zb = __popc((~xq0) & ((kk ? (1u << kk) : 1u) - 1u));
            const int  cnt0 = cnt0_base + zb;            // zeros of term-batch before i

            const float t    = x1 ? c : -c;
            const float relu = fmaxf(t, 0.0f);
            const float z    = ex2f(fabsf(c) * -2.8853902f);
            float term = -relu - 0.34657359f * lg2f(1.0f + z);

            const int cOther = x1 ? cnt0 : (i - cnt0);
            if (cOther >= 512) term = 0.0f;
            acc += term;
        }

        cnt0_base += 32 - __popc(xq0);
    }

    // gather per-js partial sums: batch l&3 spread over lanes l, l^4, l^8, l^16
    acc += __shfl_xor_sync(0xffffffffu, acc, 4);
    acc += __shfl_xor_sync(0xffffffffu, acc, 8);
    acc += __shfl_xor_sync(0xffffffffu, acc, 16);

    if (l < 4)
        out[b0 + l] = acc;
}

extern "C" void kernel_launch(void* const* d_in, const int* in_sizes, int n_in,
                              void* d_out, int out_size) {
    (void)n_in; (void)out_size;
    const int*   inputs;
    const float* eps;
    if (in_sizes[0] == Bc * Lc) {
        inputs = (const int*)d_in[0];
        eps    = (const float*)d_in[1];
    } else {
        inputs = (const int*)d_in[1];
        eps    = (const float*)d_in[0];
    }
    float* out = (float*)d_out;

    prep_eps<<<Lc, 256>>>(eps);
    prep_x<<<Bc, 256>>>(inputs);

    arqgps_main<<<Bc / 4, 32>>>(out);
}

// round 9
// speedup vs baseline: 1.8529x; 1.2650x over previous
#include <cuda_runtime.h>
#include <cstdint>
#include <cstddef>

#define Lc 1024
#define Bc 8192

// epsT[i*256 + d*128 + m]
__device__ __align__(16) float    g_epsT[Lc * 256];
// xpack[w*Bc + b] = bitmask of inputs[b, 32w .. 32w+31]
__device__ __align__(16) uint32_t g_xpack[(Lc / 32) * Bc];

// merged prep: blocks [0,1024) transpose eps; blocks [1024,2048) pack inputs
__global__ __launch_bounds__(256)
void prep_all(const float* __restrict__ eps, const int* __restrict__ x) {
    if (blockIdx.x < 1024) {
        int idx = blockIdx.x * 256 + threadIdx.x;   // idx = i*256 + dm
        int dm = idx & 255;
        int i  = idx >> 8;
        g_epsT[idx] = eps[(dm << 10) + i];          // eps[(d*128+m)*1024 + i]
    } else {
        int blk = blockIdx.x - 1024;                // 0..1023
        int b   = blk * 8 + (threadIdx.x >> 5);     // warp -> batch
        int k   = threadIdx.x & 31;
#pragma unroll 4
        for (int w = 0; w < 32; w++) {
            int v = x[(size_t)b * Lc + (w << 5) + k];
            unsigned m = __ballot_sync(0xffffffffu, v != 0);
            if (k == 0) g_xpack[w * Bc + b] = m;
        }
    }
}

static __device__ __forceinline__ uint64_t mul2(uint64_t a, uint64_t b) {
    uint64_t d; asm("mul.rn.f32x2 %0, %1, %2;" : "=l"(d) : "l"(a), "l"(b)); return d;
}
static __device__ __forceinline__ uint64_t fma2(uint64_t a, uint64_t b, uint64_t c) {
    uint64_t d; asm("fma.rn.f32x2 %0, %1, %2, %3;" : "=l"(d) : "l"(a), "l"(b), "l"(c)); return d;
}
static __device__ __forceinline__ float hadd2(uint64_t v) {
    float x, y; asm("mov.b64 {%0,%1}, %2;" : "=f"(x), "=f"(y) : "l"(v)); return x + y;
}
static __device__ __forceinline__ float ex2f(float x) {
    float y; asm("ex2.approx.ftz.f32 %0, %1;" : "=f"(y) : "f"(x)); return y;
}
static __device__ __forceinline__ float lg2f(float x) {
    float y; asm("lg2.approx.ftz.f32 %0, %1;" : "=f"(y) : "f"(x)); return y;
}

__global__ __launch_bounds__(32, 14)
void arqgps_main(float* __restrict__ out) {
    const int l    = threadIdx.x;        // 1 warp = 4 batches
    const int b0   = blockIdx.x * 4;
    const int perm = l & 3;              // slot sp tracks batch sp^perm; term-batch = perm
    const int js   = l >> 2;             // lane's step-offset within each 8-step block
    const bool h4  = (l & 4)  != 0;
    const bool h8  = (l & 8)  != 0;
    const bool h16 = (l & 16) != 0;

    const uint64_t ONE2  = 0x3f8000003f800000ull;
    const uint64_t NEG12 = 0xbf800000bf800000ull;

    uint64_t gx[4], gy[4];
#pragma unroll
    for (int sp = 0; sp < 4; sp++) { gx[sp] = ONE2; gy[sp] = ONE2; }

    float acc       = 0.0f;
    int   cnt0_base = 0;                 // zeros of term-batch before current window

    const ulonglong2* e0p = (const ulonglong2*)g_epsT + l;        // d=0, m 4l..4l+3
    const ulonglong2* e1p = e0p + 32;                             // d=1

    for (int w = 0; w < Lc / 32; w++) {
        const uint32_t xq0 = __ldg(g_xpack + w * Bc + b0 + (0 ^ perm));
        const uint32_t xq1 = __ldg(g_xpack + w * Bc + b0 + (1 ^ perm));
        const uint32_t xq2 = __ldg(g_xpack + w * Bc + b0 + (2 ^ perm));
        const uint32_t xq3 = __ldg(g_xpack + w * Bc + b0 + (3 ^ perm));

        for (int K8 = 0; K8 < 32; K8 += 8) {
            const uint32_t x0w = xq0 >> K8;
            const uint32_t x1w = xq1 >> K8;
            const uint32_t x2w = xq2 >> K8;
            const uint32_t x3w = xq3 >> K8;

            // ---- front-batched epsilon loads for the 8-step block (MLP 16) ----
            ulonglong2 E0v[8], E1v[8];
#pragma unroll
            for (int j = 0; j < 8; j++) {
                const size_t i = (size_t)((w << 5) + K8 + j) * 64;
                E0v[j] = __ldg(e0p + i);
                E1v[j] = __ldg(e1p + i);
            }

            float u[8];
#pragma unroll
            for (int j = 0; j < 8; j++) {
                const ulonglong2 E0 = E0v[j];
                const ulonglong2 E1 = E1v[j];

                const uint64_t EDx = fma2(E1.x, NEG12, E0.x);    // E0-E1
                const uint64_t EDy = fma2(E1.y, NEG12, E0.y);

                const uint32_t bj = 1u << j;
                const bool p0b = (x0w & bj) != 0;
                const bool p1b = (x1w & bj) != 0;
                const bool p2b = (x2w & bj) != 0;
                const bool p3b = (x3w & bj) != 0;

                uint64_t pd0 = fma2(EDy, gy[0], mul2(EDx, gx[0]));
                uint64_t pd1 = fma2(EDy, gy[1], mul2(EDx, gx[1]));
                uint64_t pd2 = fma2(EDy, gy[2], mul2(EDx, gx[2]));
                uint64_t pd3 = fma2(EDy, gy[3], mul2(EDx, gx[3]));

                gx[0] = mul2(gx[0], p0b ? E1.x : E0.x);
                gy[0] = mul2(gy[0], p0b ? E1.y : E0.y);
                gx[1] = mul2(gx[1], p1b ? E1.x : E0.x);
                gy[1] = mul2(gy[1], p1b ? E1.y : E0.y);
                gx[2] = mul2(gx[2], p2b ? E1.x : E0.x);
                gy[2] = mul2(gy[2], p2b ? E1.y : E0.y);
                gx[3] = mul2(gx[3], p3b ? E1.x : E0.x);
                gy[3] = mul2(gy[3], p3b ? E1.y : E0.y);

                float v0 = hadd2(pd0);
                float v1 = hadd2(pd1);
                float v2 = hadd2(pd2);
                float v3 = hadd2(pd3);

                // slot-combine: v0 = 16-m partial delta for batch (l&3)
                v0 += __shfl_xor_sync(0xffffffffu, v2, 2);
                v1 += __shfl_xor_sync(0xffffffffu, v3, 2);
                v0 += __shfl_xor_sync(0xffffffffu, v1, 1);
                u[j] = v0;
            }

            // ---- fold 8 steps across lane groups ----
            float a0, a1, a2, a3, s;
            a0 = h4 ? u[1] : u[0]; s = h4 ? u[0] : u[1];
            a0 += __shfl_xor_sync(0xffffffffu, s, 4);
            a1 = h4 ? u[3] : u[2]; s = h4 ? u[2] : u[3];
            a1 += __shfl_xor_sync(0xffffffffu, s, 4);
            a2 = h4 ? u[5] : u[4]; s = h4 ? u[4] : u[5];
            a2 += __shfl_xor_sync(0xffffffffu, s, 4);
            a3 = h4 ? u[7] : u[6]; s = h4 ? u[6] : u[7];
            a3 += __shfl_xor_sync(0xffffffffu, s, 4);
            float c0, c1;
            c0 = h8 ? a1 : a0; s = h8 ? a0 : a1;
            c0 += __shfl_xor_sync(0xffffffffu, s, 8);
            c1 = h8 ? a3 : a2; s = h8 ? a2 : a3;
            c1 += __shfl_xor_sync(0xffffffffu, s, 8);
            float c = h16 ? c1 : c0; s = h16 ? c0 : c1;
            c += __shfl_xor_sync(0xffffffffu, s, 16);
            // c = full-128m delta for (batch l&3, step K8+js)

            // ---- per-lane term ----
            const int  kk = K8 + js;
            const int  i  = (w << 5) + kk;
            const bool x1 = ((xq0 >> kk) & 1u) != 0;
            const int  zb = __popc((~xq0) & ((1u << kk) - 1u));   // kk<32 always; kk=0 -> 0
            const int  cnt0 = cnt0_base + zb;

            const float t    = x1 ? c : -c;
            const float relu = fmaxf(t, 0.0f);
            const float z    = ex2f(fabsf(c) * -2.8853902f);
            float term = -relu - 0.34657359f * lg2f(1.0f + z);

            const int cOther = x1 ? cnt0 : (i - cnt0);
            if (cOther >= 512) term = 0.0f;
            acc += term;
        }

        cnt0_base += 32 - __popc(xq0);
    }

    acc += __shfl_xor_sync(0xffffffffu, acc, 4);
    acc += __shfl_xor_sync(0xffffffffu, acc, 8);
    acc += __shfl_xor_sync(0xffffffffu, acc, 16);

    if (l < 4)
        out[b0 + l] = acc;
}

extern "C" void kernel_launch(void* const* d_in, const int* in_sizes, int n_in,
                              void* d_out, int out_size) {
    (void)n_in; (void)out_size;
    const int*   inputs;
    const float* eps;
    if (in_sizes[0] == Bc * Lc) {
        inputs = (const int*)d_in[0];
        eps    = (const float*)d_in[1];
    } else {
        inputs = (const int*)d_in[1];
        eps    = (const float*)d_in[0];
    }
    float* out = (float*)d_out;

    prep_all<<<2048, 256>>>(eps, inputs);
    arqgps_main<<<Bc / 4, 32>>>(out);
}

// round 10
// speedup vs baseline: 1.9647x; 1.0603x over previous
#include <cuda_runtime.h>
#include <cstdint>
#include <cstddef>

#define Lc 1024
#define Bc 8192

// epsT[i*256 + d*128 + m]
__device__ __align__(16) float    g_epsT[Lc * 256];
// xpack[w*Bc + b] = bitmask of inputs[b, 32w .. 32w+31]
__device__ __align__(16) uint32_t g_xpack[(Lc / 32) * Bc];

// merged prep: blocks [0,1024) transpose eps; blocks [1024,2048) pack inputs
__global__ __launch_bounds__(256)
void prep_all(const float* __restrict__ eps, const int* __restrict__ x) {
    if (blockIdx.x < 1024) {
        int idx = blockIdx.x * 256 + threadIdx.x;   // idx = i*256 + dm
        int dm = idx & 255;
        int i  = idx >> 8;
        g_epsT[idx] = eps[(dm << 10) + i];          // eps[(d*128+m)*1024 + i]
    } else {
        int blk = blockIdx.x - 1024;                // 0..1023
        int b   = blk * 8 + (threadIdx.x >> 5);     // warp -> batch
        int k   = threadIdx.x & 31;
#pragma unroll 4
        for (int w = 0; w < 32; w++) {
            int v = x[(size_t)b * Lc + (w << 5) + k];
            unsigned m = __ballot_sync(0xffffffffu, v != 0);
            if (k == 0) g_xpack[w * Bc + b] = m;
        }
    }
}

static __device__ __forceinline__ uint64_t mul2(uint64_t a, uint64_t b) {
    uint64_t d; asm("mul.rn.f32x2 %0, %1, %2;" : "=l"(d) : "l"(a), "l"(b)); return d;
}
static __device__ __forceinline__ uint64_t fma2(uint64_t a, uint64_t b, uint64_t c) {
    uint64_t d; asm("fma.rn.f32x2 %0, %1, %2, %3;" : "=l"(d) : "l"(a), "l"(b), "l"(c)); return d;
}
static __device__ __forceinline__ float hadd2(uint64_t v) {
    float x, y; asm("mov.b64 {%0,%1}, %2;" : "=f"(x), "=f"(y) : "l"(v)); return x + y;
}
static __device__ __forceinline__ float ex2f(float x) {
    float y; asm("ex2.approx.ftz.f32 %0, %1;" : "=f"(y) : "f"(x)); return y;
}
static __device__ __forceinline__ float lg2f(float x) {
    float y; asm("lg2.approx.ftz.f32 %0, %1;" : "=f"(y) : "f"(x)); return y;
}

// fold 8 step-partials across lane groups + compute the term for this lane's
// (batch, step); accumulate into acc.
static __device__ __forceinline__ void fold_term(
    const float* uu, uint32_t pxq0, int pK8, int pibase, int pcnt0,
    int js, bool h4, bool h8, bool h16, float& acc)
{
    float a0, a1, a2, a3, s;
    a0 = h4 ? uu[1] : uu[0]; s = h4 ? uu[0] : uu[1];
    a0 += __shfl_xor_sync(0xffffffffu, s, 4);
    a1 = h4 ? uu[3] : uu[2]; s = h4 ? uu[2] : uu[3];
    a1 += __shfl_xor_sync(0xffffffffu, s, 4);
    a2 = h4 ? uu[5] : uu[4]; s = h4 ? uu[4] : uu[5];
    a2 += __shfl_xor_sync(0xffffffffu, s, 4);
    a3 = h4 ? uu[7] : uu[6]; s = h4 ? uu[6] : uu[7];
    a3 += __shfl_xor_sync(0xffffffffu, s, 4);
    float c0, c1;
    c0 = h8 ? a1 : a0; s = h8 ? a0 : a1;
    c0 += __shfl_xor_sync(0xffffffffu, s, 8);
    c1 = h8 ? a3 : a2; s = h8 ? a2 : a3;
    c1 += __shfl_xor_sync(0xffffffffu, s, 8);
    float c = h16 ? c1 : c0; s = h16 ? c0 : c1;
    c += __shfl_xor_sync(0xffffffffu, s, 16);
    // c = full-128m delta for (batch l&3, step pibase + pK8 + js)

    const int  kk = pK8 + js;
    const int  i  = pibase + kk;
    const bool x1 = ((pxq0 >> kk) & 1u) != 0;
    const int  zb = __popc((~pxq0) & ((1u << kk) - 1u));
    const int  cnt0 = pcnt0 + zb;

    const float t    = x1 ? c : -c;
    const float relu = fmaxf(t, 0.0f);
    const float z    = ex2f(fabsf(c) * -2.8853902f);
    float term = -relu - 0.34657359f * lg2f(1.0f + z);

    const int cOther = x1 ? cnt0 : (i - cnt0);
    if (cOther >= 512) term = 0.0f;
    acc += term;
}

__global__ __launch_bounds__(32, 14)
void arqgps_main(float* __restrict__ out) {
    const int l    = threadIdx.x;        // 1 warp = 4 batches
    const int b0   = blockIdx.x * 4;
    const int perm = l & 3;              // slot sp tracks batch sp^perm; term-batch = perm
    const int js   = l >> 2;             // lane's step-offset within each 8-step block
    const bool h4  = (l & 4)  != 0;
    const bool h8  = (l & 8)  != 0;
    const bool h16 = (l & 16) != 0;

    const uint64_t ONE2  = 0x3f8000003f800000ull;
    const uint64_t NEG12 = 0xbf800000bf800000ull;

    uint64_t gx[4], gy[4];
#pragma unroll
    for (int sp = 0; sp < 4; sp++) { gx[sp] = ONE2; gy[sp] = ONE2; }

    float acc       = 0.0f;
    int   cnt0_base = 0;                 // zeros of term-batch before current window

    // pipeline state: previous block's partials + its term context
    float    u_prev[8];
    uint32_t pxq0   = 0;
    int      pK8    = 0, pibase = 0, pcnt0 = 0;
    bool     started = false;

    const ulonglong2* e0p = (const ulonglong2*)g_epsT + l;        // d=0, m 4l..4l+3
    const ulonglong2* e1p = e0p + 32;                             // d=1

    for (int w = 0; w < Lc / 32; w++) {
        const uint32_t xq0 = __ldg(g_xpack + w * Bc + b0 + (0 ^ perm));
        const uint32_t xq1 = __ldg(g_xpack + w * Bc + b0 + (1 ^ perm));
        const uint32_t xq2 = __ldg(g_xpack + w * Bc + b0 + (2 ^ perm));
        const uint32_t xq3 = __ldg(g_xpack + w * Bc + b0 + (3 ^ perm));

#pragma unroll
        for (int kb = 0; kb < 4; kb++) {
            const int K8 = kb << 3;
            const uint32_t x0w = xq0 >> K8;
            const uint32_t x1w = xq1 >> K8;
            const uint32_t x2w = xq2 >> K8;
            const uint32_t x3w = xq3 >> K8;

            // ---- front-batched epsilon loads for this 8-step block (MLP 16) ----
            ulonglong2 E0v[8], E1v[8];
#pragma unroll
            for (int j = 0; j < 8; j++) {
                const size_t i = (size_t)((w << 5) + K8 + j) * 64;
                E0v[j] = __ldg(e0p + i);
                E1v[j] = __ldg(e1p + i);
            }

            float u_cur[8];
#pragma unroll
            for (int j = 0; j < 8; j++) {
                const ulonglong2 E0 = E0v[j];
                const ulonglong2 E1 = E1v[j];

                const uint64_t EDx = fma2(E1.x, NEG12, E0.x);    // E0-E1
                const uint64_t EDy = fma2(E1.y, NEG12, E0.y);

                const uint32_t bj = 1u << j;
                const bool p0b = (x0w & bj) != 0;
                const bool p1b = (x1w & bj) != 0;
                const bool p2b = (x2w & bj) != 0;
                const bool p3b = (x3w & bj) != 0;

                uint64_t pd0 = fma2(EDy, gy[0], mul2(EDx, gx[0]));
                uint64_t pd1 = fma2(EDy, gy[1], mul2(EDx, gx[1]));
                uint64_t pd2 = fma2(EDy, gy[2], mul2(EDx, gx[2]));
                uint64_t pd3 = fma2(EDy, gy[3], mul2(EDx, gx[3]));

                gx[0] = mul2(gx[0], p0b ? E1.x : E0.x);
                gy[0] = mul2(gy[0], p0b ? E1.y : E0.y);
                gx[1] = mul2(gx[1], p1b ? E1.x : E0.x);
                gy[1] = mul2(gy[1], p1b ? E1.y : E0.y);
                gx[2] = mul2(gx[2], p2b ? E1.x : E0.x);
                gy[2] = mul2(gy[2], p2b ? E1.y : E0.y);
                gx[3] = mul2(gx[3], p3b ? E1.x : E0.x);
                gy[3] = mul2(gy[3], p3b ? E1.y : E0.y);

                float v0 = hadd2(pd0);
                float v1 = hadd2(pd1);
                float v2 = hadd2(pd2);
                float v3 = hadd2(pd3);

                // slot-combine: v0 = 16-m partial delta for batch (l&3)
                v0 += __shfl_xor_sync(0xffffffffu, v2, 2);
                v1 += __shfl_xor_sync(0xffffffffu, v3, 2);
                v0 += __shfl_xor_sync(0xffffffffu, v1, 1);
                u_cur[j] = v0;
            }

            // ---- deferred fold+term of the PREVIOUS block (overlaps this
            //      block's math with the prior block's shfl/MUFU latency) ----
            if (started)
                fold_term(u_prev, pxq0, pK8, pibase, pcnt0,
                          js, h4, h8, h16, acc);

#pragma unroll
            for (int j = 0; j < 8; j++) u_prev[j] = u_cur[j];
            pxq0 = xq0; pK8 = K8; pibase = w << 5; pcnt0 = cnt0_base;
            started = true;
        }

        cnt0_base += 32 - __popc(xq0);
    }

    // epilogue: fold+term of the final block
    fold_term(u_prev, pxq0, pK8, pibase, pcnt0, js, h4, h8, h16, acc);

    acc += __shfl_xor_sync(0xffffffffu, acc, 4);
    acc += __shfl_xor_sync(0xffffffffu, acc, 8);
    acc += __shfl_xor_sync(0xffffffffu, acc, 16);

    if (l < 4)
        out[b0 + l] = acc;
}

extern "C" void kernel_launch(void* const* d_in, const int* in_sizes, int n_in,
                              void* d_out, int out_size) {
    (void)n_in; (void)out_size;
    const int*   inputs;
    const float* eps;
    if (in_sizes[0] == Bc * Lc) {
        inputs = (const int*)d_in[0];
        eps    = (const float*)d_in[1];
    } else {
        inputs = (const int*)d_in[1];
        eps    = (const float*)d_in[0];
    }
    float* out = (float*)d_out;

    prep_all<<<2048, 256>>>(eps, inputs);
    arqgps_main<<<Bc / 4, 32>>>(out);
}